// round 13
// baseline (speedup 1.0000x reference)
#include <cuda_runtime.h>
#include <math.h>

#define EMB 16
#define MAXL 50
#define BMAX 32768
#define XDIM 112

// Scratch: pre-BN concatenated features per row, BN accumulators, BN affine.
__device__ float  g_x[(size_t)BMAX * XDIM];    // 14.7 MB
__device__ double g_acc[128];                  // [f][sum(16) | sumsq(16)]
__device__ float  g_bn_scale[64];
__device__ float  g_bn_shift[64];

__global__ void zero_acc_kernel() {
    if (threadIdx.x < 128) g_acc[threadIdx.x] = 0.0;
}

__global__ void fill_signal_kernel(float* out, int n) {
    int i = blockIdx.x * blockDim.x + threadIdx.x;
    if (i < n) out[i] = 0.123456f;
}

// ---------------------------------------------------------------------------
// Pool kernel: 16 lanes per row (lane = dim), 2 rows per warp, 256 thr/block.
// ---------------------------------------------------------------------------
__global__ __launch_bounds__(256) void pool_kernel(
    const int* __restrict__ user_id, const int* __restrict__ movie_id,
    const int* __restrict__ year,
    const int* __restrict__ ug, const int* __restrict__ urb_ids,
    const int* __restrict__ mg, const int* __restrict__ mt,
    const int* __restrict__ ugc, const int* __restrict__ urbc,
    const int* __restrict__ mgc, const int* __restrict__ mtc,
    const float* __restrict__ Euser, const float* __restrict__ Emovie,
    const float* __restrict__ Etag, const float* __restrict__ Egenre,
    const float* __restrict__ Eyear, const float* __restrict__ Amovie,
    int B)
{
    __shared__ float s_acc[128];
    __shared__ float s_genre[30 * 17];  // padded stride 17: conflict-free

    int tid = threadIdx.x;
    if (tid < 128) s_acc[tid] = 0.0f;
    for (int i = tid; i < 30 * EMB; i += blockDim.x)
        s_genre[(i >> 4) * 17 + (i & 15)] = Egenre[i];
    __syncthreads();

    int row = (blockIdx.x * blockDim.x + tid) >> 4;
    int d = tid & 15;
    unsigned hmask = (tid & 16) ? 0xFFFF0000u : 0x0000FFFFu;

    float v0 = 0.f, v1 = 0.f, v2 = 0.f, v3 = 0.f;

    if (row < B) {
        float* xr = g_x + (size_t)row * XDIM;

        // --- single features ---
        xr[d]      = Euser [user_id [row] * EMB + d];
        xr[16 + d] = Emovie[movie_id[row] * EMB + d];
        xr[32 + d] = Eyear [year    [row] * EMB + d];

        // --- f0: SUM over user_genre (genre table in smem) ---
        {
            int n = ugc[row];
            const int* p = ug + row * MAXL;
            float acc = 0.f;
            for (int j = 0; j < n; j++)
                acc += s_genre[p[j] * 17 + d];
            v0 = acc;
        }

        // --- f1: ATTEN over urb — two-pass softmax over all 50 positions.
        // Masked positions: aw=0 (contribute exp(0-m) to denominator), e=0.
        {
            int n = urbc[row];
            const int* p = urb_ids + row * MAXL;
            float m = 0.f;                      // masked aw = 0 participates in max
            for (int j = 0; j < n; j++)
                m = fmaxf(m, Amovie[p[j]]);
            float den = (float)(MAXL - n) * expf(0.f - m);
            float num = 0.f;
            for (int j = 0; j < n; j++) {
                int id = p[j];
                float w = expf(Amovie[id] - m);
                den += w;
                num += Emovie[id * EMB + d] * w;
            }
            v1 = num / den;
        }

        // --- f2: MAX (argmax of ||e||^2 over all 50 masked positions).
        // Warp-uniform trip count; masked positions contribute e=0, l2=0.
        {
            int n = mgc[row];
            const int* p = mg + row * MAXL;
            float bl2 = -1.f, be = 0.f;         // strict '>' = first-max (argmax)
            for (int j = 0; j < MAXL; j++) {
                int id = p[j];                   // in-bounds (array is [B,50])
                float e = (j < n) ? s_genre[id * 17 + d] : 0.f;
                float l2 = e * e;
                l2 += __shfl_xor_sync(hmask, l2, 1);
                l2 += __shfl_xor_sync(hmask, l2, 2);
                l2 += __shfl_xor_sync(hmask, l2, 4);
                l2 += __shfl_xor_sync(hmask, l2, 8);
                if (l2 > bl2) { bl2 = l2; be = e; }
            }
            v2 = be;
        }

        // --- f3: KORDER over movie_tag.
        // CRITICAL: n<=1 gives v == 0 EXACTLY in the reference (s*s - ss
        // cancels bit-exactly), so the normalized result is 0. FMA
        // contraction of s*s-ss would leave a rounding residual that the
        // normalization blows up to a unit vector. Guard n<=1 explicitly
        // and compute the cancellation with contraction-blocking intrinsics.
        {
            int n = mtc[row];
            if (n > 1) {
                const int* p = mt + row * MAXL;
                float s = 0.f, ss = 0.f;
                for (int j = 0; j < n; j++) {
                    float e = Etag[p[j] * EMB + d];
                    s  = __fadd_rn(s, e);
                    ss = __fadd_rn(ss, __fmul_rn(e, e));
                }
                float vv = 0.5f * __fadd_rn(__fmul_rn(s, s), -ss);
                float q = __fmul_rn(vv, vv);
                q += __shfl_xor_sync(hmask, q, 1);
                q += __shfl_xor_sync(hmask, q, 2);
                q += __shfl_xor_sync(hmask, q, 4);
                q += __shfl_xor_sync(hmask, q, 8);
                float nn = fmaxf(sqrtf(q), 1e-12f);
                v3 = vv / nn;
            }
            // n <= 1: v3 = 0 (matches reference exactly)
        }

        xr[48 + d] = v0;
        xr[64 + d] = v1;
        xr[80 + d] = v2;
        xr[96 + d] = v3;
    }

    // Block-level BN partial sums, then double-precision global flush
    atomicAdd(&s_acc[      d], v0);  atomicAdd(&s_acc[ 16 + d], v0 * v0);
    atomicAdd(&s_acc[ 32 + d], v1);  atomicAdd(&s_acc[ 48 + d], v1 * v1);
    atomicAdd(&s_acc[ 64 + d], v2);  atomicAdd(&s_acc[ 80 + d], v2 * v2);
    atomicAdd(&s_acc[ 96 + d], v3);  atomicAdd(&s_acc[112 + d], v3 * v3);
    __syncthreads();
    if (tid < 128) atomicAdd(&g_acc[tid], (double)s_acc[tid]);
}

// ---------------------------------------------------------------------------
// BN finalize: mean/var -> per-column scale/shift
// ---------------------------------------------------------------------------
__global__ void bn_finalize_kernel(const float* __restrict__ gamma,
                                   const float* __restrict__ beta, double invB)
{
    int c = threadIdx.x;           // 0..63
    if (c >= 64) return;
    int f = c >> 4, d = c & 15;
    double mean = g_acc[f * 32 + d] * invB;
    double var  = g_acc[f * 32 + 16 + d] * invB - mean * mean;
    float sc = gamma[c] * (float)(1.0 / sqrt(var + 1e-5));
    g_bn_scale[c] = sc;
    g_bn_shift[c] = fmaf(-(float)mean, sc, beta[c]);
}

// ---------------------------------------------------------------------------
// MLP kernel: weights staged in shared, one warp per row (grid-stride).
// ---------------------------------------------------------------------------
__global__ __launch_bounds__(256) void mlp_kernel(
    const float* __restrict__ W1, const float* __restrict__ b1,
    const float* __restrict__ W2, const float* __restrict__ b2,
    const float* __restrict__ W3, const float* __restrict__ b3,
    float* __restrict__ out, int B)
{
    __shared__ float sW1[XDIM * 64];   // 28 KB
    __shared__ float sW2[64 * 32];     // 8 KB
    __shared__ float sb1[64], sbs[64], sbsh[64];
    __shared__ float sb2[32], sW3[32];
    __shared__ float sb3;
    __shared__ float sx[8][XDIM + 4];
    __shared__ float sh[8][64];

    int tid = threadIdx.x;
    for (int i = tid; i < XDIM * 64; i += blockDim.x) sW1[i] = W1[i];
    for (int i = tid; i < 64 * 32;  i += blockDim.x) sW2[i] = W2[i];
    if (tid < 64) { sb1[tid] = b1[tid]; sbs[tid] = g_bn_scale[tid]; sbsh[tid] = g_bn_shift[tid]; }
    if (tid >= 64 && tid < 96) { sb2[tid - 64] = b2[tid - 64]; sW3[tid - 64] = W3[tid - 64]; }
    if (tid == 96) sb3 = b3[0];
    __syncthreads();

    int warp = tid >> 5, lane = tid & 31;
    int nw = blockDim.x >> 5;

    for (int row = blockIdx.x * nw + warp; row < B; row += gridDim.x * nw) {
        const float* xr = g_x + (size_t)row * XDIM;
        #pragma unroll
        for (int k = 0; k < 4; k++) {
            int i = lane + 32 * k;
            if (i < XDIM) {
                float xv = xr[i];
                if (i >= 48) { int c = i - 48; xv = fmaf(xv, sbs[c], sbsh[c]); }
                sx[warp][i] = xv;
            }
        }
        __syncwarp();

        // Layer 1
        float a0 = sb1[lane], a1 = sb1[lane + 32];
        #pragma unroll 16
        for (int i = 0; i < XDIM; i++) {
            float xv = sx[warp][i];
            a0 = fmaf(xv, sW1[i * 64 + lane],       a0);
            a1 = fmaf(xv, sW1[i * 64 + 32 + lane],  a1);
        }
        sh[warp][lane]      = fmaxf(a0, 0.f);
        sh[warp][lane + 32] = fmaxf(a1, 0.f);
        __syncwarp();

        // Layer 2
        float a = sb2[lane];
        #pragma unroll 16
        for (int k = 0; k < 64; k++)
            a = fmaf(sh[warp][k], sW2[k * 32 + lane], a);
        a = fmaxf(a, 0.f);

        // Layer 3 + sigmoid
        float t = a * sW3[lane];
        #pragma unroll
        for (int o = 16; o; o >>= 1) t += __shfl_xor_sync(0xFFFFFFFFu, t, o);
        if (lane == 0) {
            t += sb3;
            out[row] = 1.f / (1.f + expf(-t));
        }
        __syncwarp();
    }
}

// ---------------------------------------------------------------------------
// Launch
// ---------------------------------------------------------------------------
extern "C" void kernel_launch(void* const* d_in, const int* in_sizes, int n_in,
                              void* d_out, int out_size)
{
    int B = in_sizes[0];
    if (B > BMAX) B = BMAX;

    // Verify metadata ordering by size signature. On mismatch, emit a
    // distinctive constant so rel_err tells us ordering (not math) is wrong.
    bool ok = (n_in == 27)
        && in_sizes[1]  == B        && in_sizes[2]  == B
        && in_sizes[3]  == B * MAXL && in_sizes[4]  == B * MAXL
        && in_sizes[5]  == B * MAXL && in_sizes[6]  == B * MAXL
        && in_sizes[7]  == B        && in_sizes[8]  == B
        && in_sizes[9]  == B        && in_sizes[10] == B
        && in_sizes[11] == 139000 * EMB
        && in_sizes[12] == 132000 * EMB
        && in_sizes[13] == 41000 * EMB
        && in_sizes[14] == 30 * EMB
        && in_sizes[15] == 150 * EMB
        && in_sizes[16] == 132000
        && in_sizes[17] == 41000
        && in_sizes[18] == 30
        && in_sizes[19] == 64 && in_sizes[20] == 64
        && in_sizes[21] == XDIM * 64 && in_sizes[22] == 64
        && in_sizes[23] == 64 * 32   && in_sizes[24] == 32
        && in_sizes[25] == 32        && in_sizes[26] == 1;

    if (!ok) {
        fill_signal_kernel<<<(out_size + 255) / 256, 256>>>((float*)d_out, out_size);
        return;
    }

    const int* user_id  = (const int*)d_in[0];
    const int* movie_id = (const int*)d_in[1];
    const int* year     = (const int*)d_in[2];
    const int* ug       = (const int*)d_in[3];
    const int* urb      = (const int*)d_in[4];
    const int* mg       = (const int*)d_in[5];
    const int* mt       = (const int*)d_in[6];
    const int* ugc      = (const int*)d_in[7];
    const int* urbc     = (const int*)d_in[8];
    const int* mgc      = (const int*)d_in[9];
    const int* mtc      = (const int*)d_in[10];
    const float* Euser  = (const float*)d_in[11];
    const float* Emovie = (const float*)d_in[12];
    const float* Etag   = (const float*)d_in[13];
    const float* Egenre = (const float*)d_in[14];
    const float* Eyear  = (const float*)d_in[15];
    const float* Amovie = (const float*)d_in[16];
    const float* gamma  = (const float*)d_in[19];
    const float* beta   = (const float*)d_in[20];
    const float* W1     = (const float*)d_in[21];
    const float* b1     = (const float*)d_in[22];
    const float* W2     = (const float*)d_in[23];
    const float* b2     = (const float*)d_in[24];
    const float* W3     = (const float*)d_in[25];
    const float* b3     = (const float*)d_in[26];

    zero_acc_kernel<<<1, 128>>>();

    int threads = 256;
    int blocks = (B * 16 + threads - 1) / threads;
    pool_kernel<<<blocks, threads>>>(user_id, movie_id, year, ug, urb, mg, mt,
                                     ugc, urbc, mgc, mtc,
                                     Euser, Emovie, Etag, Egenre, Eyear, Amovie, B);

    bn_finalize_kernel<<<1, 64>>>(gamma, beta, 1.0 / (double)B);

    mlp_kernel<<<592, 256>>>(W1, b1, W2, b2, W3, b3, (float*)d_out, B);
}

// round 14
// speedup vs baseline: 1.5059x; 1.5059x over previous
#include <cuda_runtime.h>
#include <math.h>

#define EMB 16
#define MAXL 50
#define BMAX 32768
#define XDIM 112

// Scratch: pre-BN concatenated features per row, BN accumulators, BN affine.
__device__ float  g_x[(size_t)BMAX * XDIM];    // 14.7 MB
__device__ double g_acc[128];                  // [f][sum(16) | sumsq(16)]
__device__ float  g_bn_scale[64];
__device__ float  g_bn_shift[64];

__global__ void zero_acc_kernel() {
    if (threadIdx.x < 128) g_acc[threadIdx.x] = 0.0;
}

__global__ void fill_signal_kernel(float* out, int n) {
    int i = blockIdx.x * blockDim.x + threadIdx.x;
    if (i < n) out[i] = 0.123456f;
}

// ---------------------------------------------------------------------------
// Pool kernel: 16 lanes per row (lane = dim), 2 rows per warp, 256 thr/block.
// ---------------------------------------------------------------------------
__global__ __launch_bounds__(256) void pool_kernel(
    const int* __restrict__ user_id, const int* __restrict__ movie_id,
    const int* __restrict__ year,
    const int* __restrict__ ug, const int* __restrict__ urb_ids,
    const int* __restrict__ mg, const int* __restrict__ mt,
    const int* __restrict__ ugc, const int* __restrict__ urbc,
    const int* __restrict__ mgc, const int* __restrict__ mtc,
    const float* __restrict__ Euser, const float* __restrict__ Emovie,
    const float* __restrict__ Etag, const float* __restrict__ Egenre,
    const float* __restrict__ Eyear, const float* __restrict__ Amovie,
    int B)
{
    __shared__ float s_acc[128];
    __shared__ float s_genre[30 * 17];  // padded stride 17: conflict-free
    __shared__ float s_gl2[30];         // per-genre ||e||^2 (precomputed)

    int tid = threadIdx.x;
    if (tid < 128) s_acc[tid] = 0.0f;
    for (int i = tid; i < 30 * EMB; i += blockDim.x)
        s_genre[(i >> 4) * 17 + (i & 15)] = Egenre[i];
    __syncthreads();
    if (tid < 30) {
        // sequential-order sum of squares, contraction-blocked (matches ref rounding)
        float ss = 0.f;
        for (int d2 = 0; d2 < EMB; d2++) {
            float e = s_genre[tid * 17 + d2];
            ss = __fadd_rn(ss, __fmul_rn(e, e));
        }
        s_gl2[tid] = ss;
    }
    __syncthreads();

    int row = (blockIdx.x * blockDim.x + tid) >> 4;
    int d = tid & 15;
    unsigned hmask = (tid & 16) ? 0xFFFF0000u : 0x0000FFFFu;

    float v0 = 0.f, v1 = 0.f, v2 = 0.f, v3 = 0.f;

    if (row < B) {
        float* xr = g_x + (size_t)row * XDIM;

        // --- single features ---
        xr[d]      = Euser [user_id [row] * EMB + d];
        xr[16 + d] = Emovie[movie_id[row] * EMB + d];
        xr[32 + d] = Eyear [year    [row] * EMB + d];

        // --- f0: SUM over user_genre (genre table in smem) ---
        {
            int n = ugc[row];
            const int* p = ug + row * MAXL;
            float acc = 0.f;
            #pragma unroll 2
            for (int j = 0; j < n; j++)
                acc += s_genre[p[j] * 17 + d];
            v0 = acc;
        }

        // --- f1: ATTEN over urb — two-pass softmax over all 50 positions.
        // Masked positions: aw=0 (contribute exp(0-m) to denominator), e=0.
        {
            int n = urbc[row];
            const int* p = urb_ids + row * MAXL;
            float m = 0.f;                      // masked aw = 0 participates in max
            #pragma unroll 2
            for (int j = 0; j < n; j++)
                m = fmaxf(m, Amovie[p[j]]);
            float den = (float)(MAXL - n) * __expf(0.f - m);
            float num = 0.f;
            #pragma unroll 2
            for (int j = 0; j < n; j++) {
                int id = p[j];
                float w = __expf(Amovie[id] - m);
                den += w;
                num += Emovie[id * EMB + d] * w;
            }
            v1 = num / den;
        }

        // --- f2: MAX = argmax of ||e||^2 over valid items (masked = 0).
        // Norms are a property of the 30-row genre table -> use precomputed
        // s_gl2: scalar argmax, NO shuffles. Strict '>' with bl2=0 start:
        // first-max among positives; all-zero / n==0 -> e = 0 (matches ref).
        {
            int n = mgc[row];
            const int* p = mg + row * MAXL;
            float bl2 = 0.f; int bid = -1;
            #pragma unroll 2
            for (int j = 0; j < n; j++) {
                int id = p[j];
                float l2 = s_gl2[id];
                if (l2 > bl2) { bl2 = l2; bid = id; }
            }
            v2 = (bid >= 0) ? s_genre[bid * 17 + d] : 0.f;
        }

        // --- f3: KORDER over movie_tag.
        // n<=1 gives v == 0 EXACTLY in the reference (s*s - ss cancels
        // bit-exactly) -> guard; contraction-blocked cancellation.
        {
            int n = mtc[row];
            if (n > 1) {
                const int* p = mt + row * MAXL;
                float s = 0.f, ss = 0.f;
                #pragma unroll 2
                for (int j = 0; j < n; j++) {
                    float e = Etag[p[j] * EMB + d];
                    s  = __fadd_rn(s, e);
                    ss = __fadd_rn(ss, __fmul_rn(e, e));
                }
                float vv = 0.5f * __fadd_rn(__fmul_rn(s, s), -ss);
                float q = __fmul_rn(vv, vv);
                q += __shfl_xor_sync(hmask, q, 1);
                q += __shfl_xor_sync(hmask, q, 2);
                q += __shfl_xor_sync(hmask, q, 4);
                q += __shfl_xor_sync(hmask, q, 8);
                float nn = fmaxf(sqrtf(q), 1e-12f);
                v3 = vv / nn;
            }
        }

        xr[48 + d] = v0;
        xr[64 + d] = v1;
        xr[80 + d] = v2;
        xr[96 + d] = v3;
    }

    // Block-level BN partial sums, then double-precision global flush
    atomicAdd(&s_acc[      d], v0);  atomicAdd(&s_acc[ 16 + d], v0 * v0);
    atomicAdd(&s_acc[ 32 + d], v1);  atomicAdd(&s_acc[ 48 + d], v1 * v1);
    atomicAdd(&s_acc[ 64 + d], v2);  atomicAdd(&s_acc[ 80 + d], v2 * v2);
    atomicAdd(&s_acc[ 96 + d], v3);  atomicAdd(&s_acc[112 + d], v3 * v3);
    __syncthreads();
    if (tid < 128) atomicAdd(&g_acc[tid], (double)s_acc[tid]);
}

// ---------------------------------------------------------------------------
// BN finalize: mean/var -> per-column scale/shift
// ---------------------------------------------------------------------------
__global__ void bn_finalize_kernel(const float* __restrict__ gamma,
                                   const float* __restrict__ beta, double invB)
{
    int c = threadIdx.x;           // 0..63
    if (c >= 64) return;
    int f = c >> 4, d = c & 15;
    double mean = g_acc[f * 32 + d] * invB;
    double var  = g_acc[f * 32 + 16 + d] * invB - mean * mean;
    float sc = gamma[c] * (float)(1.0 / sqrt(var + 1e-5));
    g_bn_scale[c] = sc;
    g_bn_shift[c] = fmaf(-(float)mean, sc, beta[c]);
}

// ---------------------------------------------------------------------------
// MLP kernel v2: register-tiled block GEMM. 64 rows per block, 256 threads.
// One 29KB shared buffer reused across x -> h -> h2 phases.
// Weights streamed float4 from global (L1-resident: W1=28KB, W2=8KB).
// ---------------------------------------------------------------------------
__global__ __launch_bounds__(256) void mlp_kernel(
    const float* __restrict__ W1, const float* __restrict__ b1,
    const float* __restrict__ W2, const float* __restrict__ b2,
    const float* __restrict__ W3, const float* __restrict__ b3,
    float* __restrict__ out, int B)
{
    __shared__ float sBuf[64 * 113];   // stride 113: conflict-free columns
    __shared__ float sb1[64], sbs[64], sbsh[64];
    __shared__ float sb2[32], sW3[32];
    __shared__ float sb3v;

    int tid = threadIdx.x;
    int rowbase = blockIdx.x * 64;

    if (tid < 64) { sb1[tid] = b1[tid]; sbs[tid] = g_bn_scale[tid]; sbsh[tid] = g_bn_shift[tid]; }
    else if (tid < 96) { sb2[tid - 64] = b2[tid - 64]; sW3[tid - 64] = W3[tid - 64]; }
    else if (tid == 96) sb3v = b3[0];
    __syncthreads();

    // Stage X tile [64][112] with BN applied to cols >= 48 (float4 coalesced)
    const float4* gx4 = (const float4*)(g_x + (size_t)rowbase * XDIM);
    for (int i = tid; i < 64 * 28; i += 256) {
        int r = i / 28;
        int c = (i % 28) * 4;
        float4 v;
        if (rowbase + r < B) v = gx4[i];
        else                 v = make_float4(0.f, 0.f, 0.f, 0.f);
        if (c >= 48) {
            int cc = c - 48;
            v.x = fmaf(v.x, sbs[cc],     sbsh[cc]);
            v.y = fmaf(v.y, sbs[cc + 1], sbsh[cc + 1]);
            v.z = fmaf(v.z, sbs[cc + 2], sbsh[cc + 2]);
            v.w = fmaf(v.w, sbs[cc + 3], sbsh[cc + 3]);
        }
        float* dst = &sBuf[r * 113 + c];
        dst[0] = v.x; dst[1] = v.y; dst[2] = v.z; dst[3] = v.w;
    }
    __syncthreads();

    // ---- Layer 1: [64x112] @ [112x64], thread tile 4 rows x 4 cols ----
    {
        int tx = tid & 15, ty = tid >> 4;
        int c0 = tx * 4, r0 = ty * 4;
        float acc[4][4];
        #pragma unroll
        for (int i = 0; i < 4; i++) {
            acc[i][0] = sb1[c0]; acc[i][1] = sb1[c0 + 1];
            acc[i][2] = sb1[c0 + 2]; acc[i][3] = sb1[c0 + 3];
        }
        #pragma unroll 4
        for (int k = 0; k < XDIM; k++) {
            float4 w = *(const float4*)&W1[k * 64 + c0];
            #pragma unroll
            for (int i = 0; i < 4; i++) {
                float x = sBuf[(r0 + i) * 113 + k];
                acc[i][0] = fmaf(x, w.x, acc[i][0]);
                acc[i][1] = fmaf(x, w.y, acc[i][1]);
                acc[i][2] = fmaf(x, w.z, acc[i][2]);
                acc[i][3] = fmaf(x, w.w, acc[i][3]);
            }
        }
        __syncthreads();   // all x reads complete before overwrite
        #pragma unroll
        for (int i = 0; i < 4; i++) {
            float* dst = &sBuf[(r0 + i) * 113 + c0];
            dst[0] = fmaxf(acc[i][0], 0.f); dst[1] = fmaxf(acc[i][1], 0.f);
            dst[2] = fmaxf(acc[i][2], 0.f); dst[3] = fmaxf(acc[i][3], 0.f);
        }
        __syncthreads();
    }

    // ---- Layer 2: [64x64] @ [64x32], thread tile 2 rows x 4 cols.
    // h lives in cols 0..63; h2 written to cols 64..95 (disjoint, no race).
    {
        int tx2 = tid & 7, ty2 = tid >> 3;
        int c0 = tx2 * 4, r0 = ty2 * 2;
        float a2[2][4];
        #pragma unroll
        for (int i = 0; i < 2; i++) {
            a2[i][0] = sb2[c0]; a2[i][1] = sb2[c0 + 1];
            a2[i][2] = sb2[c0 + 2]; a2[i][3] = sb2[c0 + 3];
        }
        #pragma unroll 4
        for (int k = 0; k < 64; k++) {
            float4 w = *(const float4*)&W2[k * 32 + c0];
            #pragma unroll
            for (int i = 0; i < 2; i++) {
                float h = sBuf[(r0 + i) * 113 + k];
                a2[i][0] = fmaf(h, w.x, a2[i][0]);
                a2[i][1] = fmaf(h, w.y, a2[i][1]);
                a2[i][2] = fmaf(h, w.z, a2[i][2]);
                a2[i][3] = fmaf(h, w.w, a2[i][3]);
            }
        }
        #pragma unroll
        for (int i = 0; i < 2; i++) {
            float* dst = &sBuf[(r0 + i) * 113 + 64 + c0];
            dst[0] = fmaxf(a2[i][0], 0.f); dst[1] = fmaxf(a2[i][1], 0.f);
            dst[2] = fmaxf(a2[i][2], 0.f); dst[3] = fmaxf(a2[i][3], 0.f);
        }
        __syncthreads();
    }

    // ---- Layer 3 + sigmoid: one thread per row ----
    if (tid < 64) {
        float t = sb3v;
        const float* h2 = &sBuf[tid * 113 + 64];
        #pragma unroll 8
        for (int k = 0; k < 32; k++) t = fmaf(h2[k], sW3[k], t);
        int row = rowbase + tid;
        if (row < B) out[row] = 1.f / (1.f + expf(-t));
    }
}

// ---------------------------------------------------------------------------
// Launch
// ---------------------------------------------------------------------------
extern "C" void kernel_launch(void* const* d_in, const int* in_sizes, int n_in,
                              void* d_out, int out_size)
{
    int B = in_sizes[0];
    if (B > BMAX) B = BMAX;

    bool ok = (n_in == 27)
        && in_sizes[1]  == B        && in_sizes[2]  == B
        && in_sizes[3]  == B * MAXL && in_sizes[4]  == B * MAXL
        && in_sizes[5]  == B * MAXL && in_sizes[6]  == B * MAXL
        && in_sizes[7]  == B        && in_sizes[8]  == B
        && in_sizes[9]  == B        && in_sizes[10] == B
        && in_sizes[11] == 139000 * EMB
        && in_sizes[12] == 132000 * EMB
        && in_sizes[13] == 41000 * EMB
        && in_sizes[14] == 30 * EMB
        && in_sizes[15] == 150 * EMB
        && in_sizes[16] == 132000
        && in_sizes[17] == 41000
        && in_sizes[18] == 30
        && in_sizes[19] == 64 && in_sizes[20] == 64
        && in_sizes[21] == XDIM * 64 && in_sizes[22] == 64
        && in_sizes[23] == 64 * 32   && in_sizes[24] == 32
        && in_sizes[25] == 32        && in_sizes[26] == 1;

    if (!ok) {
        fill_signal_kernel<<<(out_size + 255) / 256, 256>>>((float*)d_out, out_size);
        return;
    }

    const int* user_id  = (const int*)d_in[0];
    const int* movie_id = (const int*)d_in[1];
    const int* year     = (const int*)d_in[2];
    const int* ug       = (const int*)d_in[3];
    const int* urb      = (const int*)d_in[4];
    const int* mg       = (const int*)d_in[5];
    const int* mt       = (const int*)d_in[6];
    const int* ugc      = (const int*)d_in[7];
    const int* urbc     = (const int*)d_in[8];
    const int* mgc      = (const int*)d_in[9];
    const int* mtc      = (const int*)d_in[10];
    const float* Euser  = (const float*)d_in[11];
    const float* Emovie = (const float*)d_in[12];
    const float* Etag   = (const float*)d_in[13];
    const float* Egenre = (const float*)d_in[14];
    const float* Eyear  = (const float*)d_in[15];
    const float* Amovie = (const float*)d_in[16];
    const float* gamma  = (const float*)d_in[19];
    const float* beta   = (const float*)d_in[20];
    const float* W1     = (const float*)d_in[21];
    const float* b1     = (const float*)d_in[22];
    const float* W2     = (const float*)d_in[23];
    const float* b2     = (const float*)d_in[24];
    const float* W3     = (const float*)d_in[25];
    const float* b3     = (const float*)d_in[26];

    zero_acc_kernel<<<1, 128>>>();

    int threads = 256;
    int blocks = (B * 16 + threads - 1) / threads;
    pool_kernel<<<blocks, threads>>>(user_id, movie_id, year, ug, urb, mg, mt,
                                     ugc, urbc, mgc, mtc,
                                     Euser, Emovie, Etag, Egenre, Eyear, Amovie, B);

    bn_finalize_kernel<<<1, 64>>>(gamma, beta, 1.0 / (double)B);

    mlp_kernel<<<(B + 63) / 64, 256>>>(W1, b1, W2, b2, W3, b3, (float*)d_out, B);
}

// round 15
// speedup vs baseline: 1.6464x; 1.0933x over previous
#include <cuda_runtime.h>
#include <math.h>

#define EMB 16
#define MAXL 50
#define BMAX 32768
#define XDIM 112

// Scratch: pre-BN concatenated features per row, BN accumulators, BN affine.
__device__ float  g_x[(size_t)BMAX * XDIM];    // 14.7 MB
__device__ double g_acc[128];                  // [f][sum(16) | sumsq(16)]
__device__ float  g_bn_scale[64];
__device__ float  g_bn_shift[64];

__global__ void zero_acc_kernel() {
    if (threadIdx.x < 128) g_acc[threadIdx.x] = 0.0;
}

__global__ void fill_signal_kernel(float* out, int n) {
    int i = blockIdx.x * blockDim.x + threadIdx.x;
    if (i < n) out[i] = 0.123456f;
}

// ---------------------------------------------------------------------------
// Pool kernel v2: 16 lanes per row, 16 rows per block (256 threads).
// Phase 1 (cooperative, lane-parallel over items): cache indices in smem,
// gather Amovie once per item, compute softmax m/w/den once per item,
// lane-parallel argmax for max-pool. Phase 2 (per-dim): LDS broadcasts +
// essential row gathers only.
// ---------------------------------------------------------------------------
__global__ __launch_bounds__(256) void pool_kernel(
    const int* __restrict__ user_id, const int* __restrict__ movie_id,
    const int* __restrict__ year,
    const int* __restrict__ ug, const int* __restrict__ urb_ids,
    const int* __restrict__ mg, const int* __restrict__ mt,
    const int* __restrict__ ugc, const int* __restrict__ urbc,
    const int* __restrict__ mgc, const int* __restrict__ mtc,
    const float* __restrict__ Euser, const float* __restrict__ Emovie,
    const float* __restrict__ Etag, const float* __restrict__ Egenre,
    const float* __restrict__ Eyear, const float* __restrict__ Amovie,
    int B)
{
    __shared__ float s_acc[128];
    __shared__ float s_genre[30 * 17];  // padded stride 17: conflict-free
    __shared__ float s_gl2[30];         // per-genre ||e||^2
    __shared__ int   s_uidx[16][50];
    __shared__ float s_w[16][50];
    __shared__ int   s_mtidx[16][50];
    __shared__ int   s_ugidx[16][50];

    int tid = threadIdx.x;
    if (tid < 128) s_acc[tid] = 0.0f;
    for (int i = tid; i < 30 * EMB; i += 256)
        s_genre[(i >> 4) * 17 + (i & 15)] = Egenre[i];
    __syncthreads();
    if (tid < 30) {
        // sequential, contraction-blocked (matches ref rounding)
        float ss = 0.f;
        for (int d2 = 0; d2 < EMB; d2++) {
            float e = s_genre[tid * 17 + d2];
            ss = __fadd_rn(ss, __fmul_rn(e, e));
        }
        s_gl2[tid] = ss;
    }
    __syncthreads();

    int r = tid >> 4;            // local row 0..15
    int d = tid & 15;            // dim lane
    int row = blockIdx.x * 16 + r;
    bool valid = row < B;
    int rowc = valid ? row : (B - 1);
    unsigned hmask = (tid & 16) ? 0xFFFF0000u : 0x0000FFFFu;

    int n_ug  = ugc [rowc];
    int n_urb = urbc[rowc];
    int n_mg  = mgc [rowc];
    int n_mt  = mtc [rowc];
    const int* pug = ug      + rowc * MAXL;
    const int* pu  = urb_ids + rowc * MAXL;
    const int* pg  = mg      + rowc * MAXL;
    const int* pt  = mt      + rowc * MAXL;

    // ---- Phase 1: cooperative prefetch (lane d handles items d, d+16, ...)
    for (int j = d; j < n_ug; j += 16) s_ugidx[r][j] = pug[j];
    for (int j = d; j < n_mt; j += 16) s_mtidx[r][j] = pt[j];

    // urb: indices + attention values, local max
    float lm = 0.f;                       // masked aw = 0 participates in max
    for (int j = d; j < n_urb; j += 16) {
        int id = pu[j];
        float a = Amovie[id];
        s_uidx[r][j] = id;
        s_w[r][j] = a;
        lm = fmaxf(lm, a);
    }
    #pragma unroll
    for (int o = 8; o; o >>= 1)
        lm = fmaxf(lm, __shfl_xor_sync(hmask, lm, o));

    // exp weights (once per item) + denominator
    float lden = 0.f;
    for (int j = d; j < n_urb; j += 16) {
        float w = __expf(s_w[r][j] - lm);   // reads own writes only
        s_w[r][j] = w;
        lden += w;
    }
    #pragma unroll
    for (int o = 8; o; o >>= 1)
        lden += __shfl_xor_sync(hmask, lden, o);
    float den = lden + (float)(MAXL - n_urb) * __expf(-lm);

    // mg: lane-parallel argmax of ||e||^2; first-max tie-break by smallest j
    float bl2 = 0.f; int bid = -1; int bj = 0x7FFFFFFF;
    for (int j = d; j < n_mg; j += 16) {
        int id = pg[j];
        float l2 = s_gl2[id];
        if (l2 > bl2) { bl2 = l2; bid = id; bj = j; }
    }
    #pragma unroll
    for (int o = 8; o; o >>= 1) {
        float ol2 = __shfl_xor_sync(hmask, bl2, o);
        int   oid = __shfl_xor_sync(hmask, bid, o);
        int   oj  = __shfl_xor_sync(hmask, bj,  o);
        if (ol2 > bl2 || (ol2 == bl2 && oj < bj)) { bl2 = ol2; bid = oid; bj = oj; }
    }

    __syncwarp();   // smem item caches visible across the half-warps

    // ---- Phase 2: per-dim work
    float v0 = 0.f, v1 = 0.f, v2 = 0.f, v3 = 0.f;

    if (valid) {
        float* xr = g_x + (size_t)row * XDIM;

        // singles
        xr[d]      = Euser [user_id [row] * EMB + d];
        xr[16 + d] = Emovie[movie_id[row] * EMB + d];
        xr[32 + d] = Eyear [year    [row] * EMB + d];

        // f0: SUM over user_genre (smem table, smem idx)
        {
            float acc = 0.f;
            #pragma unroll 4
            for (int j = 0; j < n_ug; j++)
                acc += s_genre[s_ugidx[r][j] * 17 + d];
            v0 = acc;
        }

        // f1: ATTEN — weights precomputed; one gather per item
        {
            float num = 0.f;
            #pragma unroll 4
            for (int j = 0; j < n_urb; j++)
                num += Emovie[s_uidx[r][j] * EMB + d] * s_w[r][j];
            v1 = num / den;
        }

        // f2: MAX — argmax id already known
        v2 = (bid >= 0) ? s_genre[bid * 17 + d] : 0.f;

        // f3: KORDER — n<=1 gives exact 0 in ref (cancellation); guard +
        // contraction-blocked arithmetic.
        if (n_mt > 1) {
            float s = 0.f, ss = 0.f;
            #pragma unroll 4
            for (int j = 0; j < n_mt; j++) {
                float e = Etag[s_mtidx[r][j] * EMB + d];
                s  = __fadd_rn(s, e);
                ss = __fadd_rn(ss, __fmul_rn(e, e));
            }
            float vv = 0.5f * __fadd_rn(__fmul_rn(s, s), -ss);
            float q = __fmul_rn(vv, vv);
            q += __shfl_xor_sync(hmask, q, 1);
            q += __shfl_xor_sync(hmask, q, 2);
            q += __shfl_xor_sync(hmask, q, 4);
            q += __shfl_xor_sync(hmask, q, 8);
            float nn = fmaxf(sqrtf(q), 1e-12f);
            v3 = vv / nn;
        }

        xr[48 + d] = v0;
        xr[64 + d] = v1;
        xr[80 + d] = v2;
        xr[96 + d] = v3;
    }

    // Block-level BN partial sums, then double-precision global flush
    atomicAdd(&s_acc[      d], v0);  atomicAdd(&s_acc[ 16 + d], v0 * v0);
    atomicAdd(&s_acc[ 32 + d], v1);  atomicAdd(&s_acc[ 48 + d], v1 * v1);
    atomicAdd(&s_acc[ 64 + d], v2);  atomicAdd(&s_acc[ 80 + d], v2 * v2);
    atomicAdd(&s_acc[ 96 + d], v3);  atomicAdd(&s_acc[112 + d], v3 * v3);
    __syncthreads();
    if (tid < 128) atomicAdd(&g_acc[tid], (double)s_acc[tid]);
}

// ---------------------------------------------------------------------------
// BN finalize: mean/var -> per-column scale/shift
// ---------------------------------------------------------------------------
__global__ void bn_finalize_kernel(const float* __restrict__ gamma,
                                   const float* __restrict__ beta, double invB)
{
    int c = threadIdx.x;           // 0..63
    if (c >= 64) return;
    int f = c >> 4, d = c & 15;
    double mean = g_acc[f * 32 + d] * invB;
    double var  = g_acc[f * 32 + 16 + d] * invB - mean * mean;
    float sc = gamma[c] * (float)(1.0 / sqrt(var + 1e-5));
    g_bn_scale[c] = sc;
    g_bn_shift[c] = fmaf(-(float)mean, sc, beta[c]);
}

// ---------------------------------------------------------------------------
// MLP kernel v3: 32 rows per block (1024 blocks -> 2 balanced waves),
// register-tiled GEMM, weights streamed float4 (L1-resident).
// ---------------------------------------------------------------------------
__global__ __launch_bounds__(256) void mlp_kernel(
    const float* __restrict__ W1, const float* __restrict__ b1,
    const float* __restrict__ W2, const float* __restrict__ b2,
    const float* __restrict__ W3, const float* __restrict__ b3,
    float* __restrict__ out, int B)
{
    __shared__ float sBuf[32 * 113];   // stride 113: conflict-free
    __shared__ float sb1[64], sbs[64], sbsh[64];
    __shared__ float sb2[32], sW3[32];
    __shared__ float sb3v;

    int tid = threadIdx.x;
    int rowbase = blockIdx.x * 32;

    if (tid < 64) { sb1[tid] = b1[tid]; sbs[tid] = g_bn_scale[tid]; sbsh[tid] = g_bn_shift[tid]; }
    else if (tid < 96) { sb2[tid - 64] = b2[tid - 64]; sW3[tid - 64] = W3[tid - 64]; }
    else if (tid == 96) sb3v = b3[0];
    __syncthreads();

    // Stage X tile [32][112], BN applied to cols >= 48 (float4 coalesced)
    const float4* gx4 = (const float4*)(g_x + (size_t)rowbase * XDIM);
    for (int i = tid; i < 32 * 28; i += 256) {
        int rr = i / 28;
        int c = (i % 28) * 4;
        float4 v;
        if (rowbase + rr < B) v = gx4[i];
        else                  v = make_float4(0.f, 0.f, 0.f, 0.f);
        if (c >= 48) {
            int cc = c - 48;
            v.x = fmaf(v.x, sbs[cc],     sbsh[cc]);
            v.y = fmaf(v.y, sbs[cc + 1], sbsh[cc + 1]);
            v.z = fmaf(v.z, sbs[cc + 2], sbsh[cc + 2]);
            v.w = fmaf(v.w, sbs[cc + 3], sbsh[cc + 3]);
        }
        float* dst = &sBuf[rr * 113 + c];
        dst[0] = v.x; dst[1] = v.y; dst[2] = v.z; dst[3] = v.w;
    }
    __syncthreads();

    // ---- Layer 1: [32x112] @ [112x64], thread tile 2 rows x 4 cols ----
    {
        int tx = tid & 15, ty = tid >> 4;
        int c0 = tx * 4, r0 = ty * 2;
        float acc[2][4];
        #pragma unroll
        for (int i = 0; i < 2; i++) {
            acc[i][0] = sb1[c0];     acc[i][1] = sb1[c0 + 1];
            acc[i][2] = sb1[c0 + 2]; acc[i][3] = sb1[c0 + 3];
        }
        #pragma unroll 4
        for (int k = 0; k < XDIM; k++) {
            float4 w = *(const float4*)&W1[k * 64 + c0];
            float x0 = sBuf[r0 * 113 + k];
            float x1 = sBuf[(r0 + 1) * 113 + k];
            acc[0][0] = fmaf(x0, w.x, acc[0][0]);
            acc[0][1] = fmaf(x0, w.y, acc[0][1]);
            acc[0][2] = fmaf(x0, w.z, acc[0][2]);
            acc[0][3] = fmaf(x0, w.w, acc[0][3]);
            acc[1][0] = fmaf(x1, w.x, acc[1][0]);
            acc[1][1] = fmaf(x1, w.y, acc[1][1]);
            acc[1][2] = fmaf(x1, w.z, acc[1][2]);
            acc[1][3] = fmaf(x1, w.w, acc[1][3]);
        }
        __syncthreads();   // all x reads complete before overwrite
        #pragma unroll
        for (int i = 0; i < 2; i++) {
            float* dst = &sBuf[(r0 + i) * 113 + c0];
            dst[0] = fmaxf(acc[i][0], 0.f); dst[1] = fmaxf(acc[i][1], 0.f);
            dst[2] = fmaxf(acc[i][2], 0.f); dst[3] = fmaxf(acc[i][3], 0.f);
        }
        __syncthreads();
    }

    // ---- Layer 2: [32x64] @ [64x32], thread tile 1 row x 4 cols.
    // h in cols 0..63; h2 written to cols 64..95 (disjoint).
    {
        int tx2 = tid & 7, ty2 = tid >> 3;   // 0..7 cols-group, 0..31 row
        int c0 = tx2 * 4, r0 = ty2;
        float a2[4] = { sb2[c0], sb2[c0 + 1], sb2[c0 + 2], sb2[c0 + 3] };
        #pragma unroll 8
        for (int k = 0; k < 64; k++) {
            float4 w = *(const float4*)&W2[k * 32 + c0];
            float h = sBuf[r0 * 113 + k];
            a2[0] = fmaf(h, w.x, a2[0]);
            a2[1] = fmaf(h, w.y, a2[1]);
            a2[2] = fmaf(h, w.z, a2[2]);
            a2[3] = fmaf(h, w.w, a2[3]);
        }
        float* dst = &sBuf[r0 * 113 + 64 + c0];
        dst[0] = fmaxf(a2[0], 0.f); dst[1] = fmaxf(a2[1], 0.f);
        dst[2] = fmaxf(a2[2], 0.f); dst[3] = fmaxf(a2[3], 0.f);
        __syncthreads();
    }

    // ---- Layer 3 + sigmoid: one thread per row ----
    if (tid < 32) {
        float t = sb3v;
        const float* h2 = &sBuf[tid * 113 + 64];
        #pragma unroll 8
        for (int k = 0; k < 32; k++) t = fmaf(h2[k], sW3[k], t);
        int row = rowbase + tid;
        if (row < B) out[row] = 1.f / (1.f + expf(-t));
    }
}

// ---------------------------------------------------------------------------
// Launch
// ---------------------------------------------------------------------------
extern "C" void kernel_launch(void* const* d_in, const int* in_sizes, int n_in,
                              void* d_out, int out_size)
{
    int B = in_sizes[0];
    if (B > BMAX) B = BMAX;

    bool ok = (n_in == 27)
        && in_sizes[1]  == B        && in_sizes[2]  == B
        && in_sizes[3]  == B * MAXL && in_sizes[4]  == B * MAXL
        && in_sizes[5]  == B * MAXL && in_sizes[6]  == B * MAXL
        && in_sizes[7]  == B        && in_sizes[8]  == B
        && in_sizes[9]  == B        && in_sizes[10] == B
        && in_sizes[11] == 139000 * EMB
        && in_sizes[12] == 132000 * EMB
        && in_sizes[13] == 41000 * EMB
        && in_sizes[14] == 30 * EMB
        && in_sizes[15] == 150 * EMB
        && in_sizes[16] == 132000
        && in_sizes[17] == 41000
        && in_sizes[18] == 30
        && in_sizes[19] == 64 && in_sizes[20] == 64
        && in_sizes[21] == XDIM * 64 && in_sizes[22] == 64
        && in_sizes[23] == 64 * 32   && in_sizes[24] == 32
        && in_sizes[25] == 32        && in_sizes[26] == 1;

    if (!ok) {
        fill_signal_kernel<<<(out_size + 255) / 256, 256>>>((float*)d_out, out_size);
        return;
    }

    const int* user_id  = (const int*)d_in[0];
    const int* movie_id = (const int*)d_in[1];
    const int* year     = (const int*)d_in[2];
    const int* ug       = (const int*)d_in[3];
    const int* urb      = (const int*)d_in[4];
    const int* mg       = (const int*)d_in[5];
    const int* mt       = (const int*)d_in[6];
    const int* ugc      = (const int*)d_in[7];
    const int* urbc     = (const int*)d_in[8];
    const int* mgc      = (const int*)d_in[9];
    const int* mtc      = (const int*)d_in[10];
    const float* Euser  = (const float*)d_in[11];
    const float* Emovie = (const float*)d_in[12];
    const float* Etag   = (const float*)d_in[13];
    const float* Egenre = (const float*)d_in[14];
    const float* Eyear  = (const float*)d_in[15];
    const float* Amovie = (const float*)d_in[16];
    const float* gamma  = (const float*)d_in[19];
    const float* beta   = (const float*)d_in[20];
    const float* W1     = (const float*)d_in[21];
    const float* b1     = (const float*)d_in[22];
    const float* W2     = (const float*)d_in[23];
    const float* b2     = (const float*)d_in[24];
    const float* W3     = (const float*)d_in[25];
    const float* b3     = (const float*)d_in[26];

    zero_acc_kernel<<<1, 128>>>();

    pool_kernel<<<(B + 15) / 16, 256>>>(user_id, movie_id, year, ug, urb, mg, mt,
                                        ugc, urbc, mgc, mtc,
                                        Euser, Emovie, Etag, Egenre, Eyear, Amovie, B);

    bn_finalize_kernel<<<1, 64>>>(gamma, beta, 1.0 / (double)B);

    mlp_kernel<<<(B + 31) / 32, 256>>>(W1, b1, W2, b2, W3, b3, (float*)d_out, B);
}

// round 17
// speedup vs baseline: 2.0802x; 1.2635x over previous
#include <cuda_runtime.h>
#include <math.h>

#define EMB 16
#define MAXL 50
#define BMAX 32768
#define XDIM 112

// Scratch: pre-BN concatenated features per row, BN accumulators, BN affine.
__device__ float  g_x[(size_t)BMAX * XDIM];    // 14.7 MB
__device__ double g_acc[128];                  // [f][sum(16) | sumsq(16)]
__device__ float  g_bn_scale[64];
__device__ float  g_bn_shift[64];

__global__ void zero_acc_kernel() {
    if (threadIdx.x < 128) g_acc[threadIdx.x] = 0.0;
}

__global__ void fill_signal_kernel(float* out, int n) {
    int i = blockIdx.x * blockDim.x + threadIdx.x;
    if (i < n) out[i] = 0.123456f;
}

// Inline function (not macro): avoids preprocessor capture of '.w' members.
__device__ __forceinline__ void fma4(float4& a, float s, const float4& v) {
    a.x = fmaf(s, v.x, a.x);
    a.y = fmaf(s, v.y, a.y);
    a.z = fmaf(s, v.z, a.z);
    a.w = fmaf(s, v.w, a.w);
}

__device__ __forceinline__ void red4_full(float4& a, int o) {
    a.x += __shfl_xor_sync(0xffffffffu, a.x, o);
    a.y += __shfl_xor_sync(0xffffffffu, a.y, o);
    a.z += __shfl_xor_sync(0xffffffffu, a.z, o);
    a.w += __shfl_xor_sync(0xffffffffu, a.w, o);
}

// ---------------------------------------------------------------------------
// Pool kernel v3: 4 lanes per row (each lane = 4 dims, float4 gathers),
// 8 rows per warp, 64 rows per block (256 threads).
// ---------------------------------------------------------------------------
__global__ __launch_bounds__(256) void pool_kernel(
    const int* __restrict__ user_id, const int* __restrict__ movie_id,
    const int* __restrict__ year,
    const int* __restrict__ ug, const int* __restrict__ urb_ids,
    const int* __restrict__ mg, const int* __restrict__ mt,
    const int* __restrict__ ugc, const int* __restrict__ urbc,
    const int* __restrict__ mgc, const int* __restrict__ mtc,
    const float* __restrict__ Euser, const float* __restrict__ Emovie,
    const float* __restrict__ Etag, const float* __restrict__ Egenre,
    const float* __restrict__ Eyear, const float* __restrict__ Amovie,
    int B)
{
    __shared__ float s_acc[128];
    __shared__ float s_genre[30 * 20];  // stride 20: float4-aligned rows
    __shared__ float s_gl2[30];
    __shared__ float s_w[64][50];       // attention weights per local row

    int tid = threadIdx.x;
    if (tid < 128) s_acc[tid] = 0.0f;
    for (int i = tid; i < 30 * EMB; i += 256)
        s_genre[(i >> 4) * 20 + (i & 15)] = Egenre[i];
    __syncthreads();
    if (tid < 30) {
        // sequential, contraction-blocked (matches ref rounding)
        float ss = 0.f;
        for (int d2 = 0; d2 < EMB; d2++) {
            float e = s_genre[tid * 20 + d2];
            ss = __fadd_rn(ss, __fmul_rn(e, e));
        }
        s_gl2[tid] = ss;
    }
    __syncthreads();

    int lane = tid & 31;
    int d4 = lane & 3;                 // dims 4*d4 .. 4*d4+3
    int c0 = d4 * 4;
    int lr = (tid >> 5) * 8 + (lane >> 2);  // local row 0..63
    int row = blockIdx.x * 64 + lr;
    bool valid = row < B;
    int rowc = valid ? row : (B - 1);
    unsigned gmask = 0xFu << (lane & ~3);   // this row's 4-lane group

    int n_ug  = ugc [rowc];
    int n_urb = urbc[rowc];
    int n_mg  = mgc [rowc];
    int n_mt  = mtc [rowc];
    const int* pug = ug      + rowc * MAXL;
    const int* pu  = urb_ids + rowc * MAXL;
    const int* pg  = mg      + rowc * MAXL;
    const int* pt  = mt      + rowc * MAXL;

    // ---- Phase 1a: attention weights (lane d4 handles items d4, d4+4, ...)
    float lm = 0.f;                    // masked aw = 0 participates in max
    for (int j = d4; j < n_urb; j += 4) {
        float a = Amovie[pu[j]];
        s_w[lr][j] = a;
        lm = fmaxf(lm, a);
    }
    lm = fmaxf(lm, __shfl_xor_sync(0xffffffffu, lm, 1));
    lm = fmaxf(lm, __shfl_xor_sync(0xffffffffu, lm, 2));
    float lden = 0.f;
    for (int j = d4; j < n_urb; j += 4) {
        float w = __expf(s_w[lr][j] - lm);   // reads own writes only
        s_w[lr][j] = w;
        lden += w;
    }
    lden += __shfl_xor_sync(0xffffffffu, lden, 1);
    lden += __shfl_xor_sync(0xffffffffu, lden, 2);
    float den = lden + (float)(MAXL - n_urb) * __expf(-lm);

    // ---- Phase 1b: max-pool argmax of ||e||^2 (first-max = smallest j)
    float bl2 = 0.f; int bid = -1; int bj = 0x7FFFFFFF;
    for (int j = d4; j < n_mg; j += 4) {
        int id = pg[j];
        float l2 = s_gl2[id];
        if (l2 > bl2) { bl2 = l2; bid = id; bj = j; }
    }
    #pragma unroll
    for (int o = 1; o <= 2; o <<= 1) {
        float ol2 = __shfl_xor_sync(0xffffffffu, bl2, o);
        int   oid = __shfl_xor_sync(0xffffffffu, bid, o);
        int   oj  = __shfl_xor_sync(0xffffffffu, bj,  o);
        if (ol2 > bl2 || (ol2 == bl2 && oj < bj)) { bl2 = ol2; bid = oid; bj = oj; }
    }
    __syncwarp();

    // ---- Phase 2: per-dim work (float4 per lane, 8 rows per warp-instr)
    float4 v0 = make_float4(0.f, 0.f, 0.f, 0.f);
    float4 v1 = v0, v2 = v0, v3 = v0;

    if (valid) {
        float* xr = g_x + (size_t)row * XDIM;

        // singles
        *(float4*)&xr[c0]      = *(const float4*)&Euser [user_id [row] * EMB + c0];
        *(float4*)&xr[16 + c0] = *(const float4*)&Emovie[movie_id[row] * EMB + c0];
        *(float4*)&xr[32 + c0] = *(const float4*)&Eyear [year    [row] * EMB + c0];

        // f0: SUM over user_genre (smem table)
        #pragma unroll 4
        for (int j = 0; j < n_ug; j++) {
            float4 g = *(const float4*)&s_genre[pug[j] * 20 + c0];
            v0.x += g.x; v0.y += g.y; v0.z += g.z; v0.w += g.w;
        }

        // f1: ATTEN — weights precomputed; one LDG.128 per item per row
        #pragma unroll 4
        for (int j = 0; j < n_urb; j++) {
            float w = s_w[lr][j];
            float4 e = *(const float4*)&Emovie[pu[j] * EMB + c0];
            fma4(v1, w, e);
        }
        {
            float inv = 1.f / den;
            v1.x *= inv; v1.y *= inv; v1.z *= inv; v1.w *= inv;
        }

        // f2: MAX — argmax id known
        if (bid >= 0) v2 = *(const float4*)&s_genre[bid * 20 + c0];

        // f3: KORDER — n<=1 gives exact 0 in ref (cancellation); guard +
        // contraction-blocked arithmetic (sequential per-dim order = ref).
        if (n_mt > 1) {
            float4 s4 = make_float4(0.f, 0.f, 0.f, 0.f);
            float4 ss4 = s4;
            #pragma unroll 4
            for (int j = 0; j < n_mt; j++) {
                float4 e = *(const float4*)&Etag[pt[j] * EMB + c0];
                s4.x  = __fadd_rn(s4.x,  e.x); ss4.x = __fadd_rn(ss4.x, __fmul_rn(e.x, e.x));
                s4.y  = __fadd_rn(s4.y,  e.y); ss4.y = __fadd_rn(ss4.y, __fmul_rn(e.y, e.y));
                s4.z  = __fadd_rn(s4.z,  e.z); ss4.z = __fadd_rn(ss4.z, __fmul_rn(e.z, e.z));
                s4.w  = __fadd_rn(s4.w,  e.w); ss4.w = __fadd_rn(ss4.w, __fmul_rn(e.w, e.w));
            }
            float4 vv;
            vv.x = 0.5f * __fadd_rn(__fmul_rn(s4.x, s4.x), -ss4.x);
            vv.y = 0.5f * __fadd_rn(__fmul_rn(s4.y, s4.y), -ss4.y);
            vv.z = 0.5f * __fadd_rn(__fmul_rn(s4.z, s4.z), -ss4.z);
            vv.w = 0.5f * __fadd_rn(__fmul_rn(s4.w, s4.w), -ss4.w);
            float q = __fmul_rn(vv.x, vv.x) + __fmul_rn(vv.y, vv.y)
                    + __fmul_rn(vv.z, vv.z) + __fmul_rn(vv.w, vv.w);
            q += __shfl_xor_sync(gmask, q, 1);   // group-converged here
            q += __shfl_xor_sync(gmask, q, 2);
            float nn = fmaxf(sqrtf(q), 1e-12f);
            v3.x = vv.x / nn; v3.y = vv.y / nn; v3.z = vv.z / nn; v3.w = vv.w / nn;
        }

        *(float4*)&xr[48 + c0] = v0;
        *(float4*)&xr[64 + c0] = v1;
        *(float4*)&xr[80 + c0] = v2;
        *(float4*)&xr[96 + c0] = v3;
    }

    // ---- BN stats: pre-reduce across the warp's 8 rows, then shared atomics
    float4 p0, p1, p2, p3;
    p0.x = v0.x * v0.x; p0.y = v0.y * v0.y; p0.z = v0.z * v0.z; p0.w = v0.w * v0.w;
    p1.x = v1.x * v1.x; p1.y = v1.y * v1.y; p1.z = v1.z * v1.z; p1.w = v1.w * v1.w;
    p2.x = v2.x * v2.x; p2.y = v2.y * v2.y; p2.z = v2.z * v2.z; p2.w = v2.w * v2.w;
    p3.x = v3.x * v3.x; p3.y = v3.y * v3.y; p3.z = v3.z * v3.z; p3.w = v3.w * v3.w;
    #pragma unroll
    for (int o = 4; o <= 16; o <<= 1) {
        red4_full(v0, o); red4_full(v1, o); red4_full(v2, o); red4_full(v3, o);
        red4_full(p0, o); red4_full(p1, o); red4_full(p2, o); red4_full(p3, o);
    }
    if ((lane >> 2) == 0) {
        atomicAdd(&s_acc[      c0    ], v0.x); atomicAdd(&s_acc[      c0 + 1], v0.y);
        atomicAdd(&s_acc[      c0 + 2], v0.z); atomicAdd(&s_acc[      c0 + 3], v0.w);
        atomicAdd(&s_acc[ 16 + c0    ], p0.x); atomicAdd(&s_acc[ 16 + c0 + 1], p0.y);
        atomicAdd(&s_acc[ 16 + c0 + 2], p0.z); atomicAdd(&s_acc[ 16 + c0 + 3], p0.w);
        atomicAdd(&s_acc[ 32 + c0    ], v1.x); atomicAdd(&s_acc[ 32 + c0 + 1], v1.y);
        atomicAdd(&s_acc[ 32 + c0 + 2], v1.z); atomicAdd(&s_acc[ 32 + c0 + 3], v1.w);
        atomicAdd(&s_acc[ 48 + c0    ], p1.x); atomicAdd(&s_acc[ 48 + c0 + 1], p1.y);
        atomicAdd(&s_acc[ 48 + c0 + 2], p1.z); atomicAdd(&s_acc[ 48 + c0 + 3], p1.w);
        atomicAdd(&s_acc[ 64 + c0    ], v2.x); atomicAdd(&s_acc[ 64 + c0 + 1], v2.y);
        atomicAdd(&s_acc[ 64 + c0 + 2], v2.z); atomicAdd(&s_acc[ 64 + c0 + 3], v2.w);
        atomicAdd(&s_acc[ 80 + c0    ], p2.x); atomicAdd(&s_acc[ 80 + c0 + 1], p2.y);
        atomicAdd(&s_acc[ 80 + c0 + 2], p2.z); atomicAdd(&s_acc[ 80 + c0 + 3], p2.w);
        atomicAdd(&s_acc[ 96 + c0    ], v3.x); atomicAdd(&s_acc[ 96 + c0 + 1], v3.y);
        atomicAdd(&s_acc[ 96 + c0 + 2], v3.z); atomicAdd(&s_acc[ 96 + c0 + 3], v3.w);
        atomicAdd(&s_acc[112 + c0    ], p3.x); atomicAdd(&s_acc[112 + c0 + 1], p3.y);
        atomicAdd(&s_acc[112 + c0 + 2], p3.z); atomicAdd(&s_acc[112 + c0 + 3], p3.w);
    }
    __syncthreads();
    if (tid < 128) atomicAdd(&g_acc[tid], (double)s_acc[tid]);
}

// ---------------------------------------------------------------------------
// BN finalize: mean/var -> per-column scale/shift
// ---------------------------------------------------------------------------
__global__ void bn_finalize_kernel(const float* __restrict__ gamma,
                                   const float* __restrict__ beta, double invB)
{
    int c = threadIdx.x;           // 0..63
    if (c >= 64) return;
    int f = c >> 4, d = c & 15;
    double mean = g_acc[f * 32 + d] * invB;
    double var  = g_acc[f * 32 + 16 + d] * invB - mean * mean;
    float sc = gamma[c] * (float)(1.0 / sqrt(var + 1e-5));
    g_bn_scale[c] = sc;
    g_bn_shift[c] = fmaf(-(float)mean, sc, beta[c]);
}

// ---------------------------------------------------------------------------
// MLP kernel v4: 64 rows/block, 4x4 register tiles, float4 on BOTH operands
// (4 LDS.128 + 4 LDG.128 per 64 FMAs). h reuses the x buffer (stride 68).
// ---------------------------------------------------------------------------
__global__ __launch_bounds__(256) void mlp_kernel(
    const float* __restrict__ W1, const float* __restrict__ b1,
    const float* __restrict__ W2, const float* __restrict__ b2,
    const float* __restrict__ W3, const float* __restrict__ b3,
    float* __restrict__ out, int B)
{
    __shared__ float sX[64 * 116];     // x (stride 116) -> reused as h (stride 68)
    __shared__ float sH2[64 * 36];
    __shared__ float sb1[64], sbs[64], sbsh[64];
    __shared__ float sb2[32], sW3[32];
    __shared__ float sb3v;

    int tid = threadIdx.x;
    int rowbase = blockIdx.x * 64;

    if (tid < 64) { sb1[tid] = b1[tid]; sbs[tid] = g_bn_scale[tid]; sbsh[tid] = g_bn_shift[tid]; }
    else if (tid < 96) { sb2[tid - 64] = b2[tid - 64]; sW3[tid - 64] = W3[tid - 64]; }
    else if (tid == 96) sb3v = b3[0];
    __syncthreads();

    // Stage X tile [64][112] with BN on cols >= 48
    const float4* gx4 = (const float4*)(g_x + (size_t)rowbase * XDIM);
    for (int i = tid; i < 64 * 28; i += 256) {
        int rr = i / 28;
        int c = (i % 28) * 4;
        float4 v;
        if (rowbase + rr < B) v = gx4[i];
        else                  v = make_float4(0.f, 0.f, 0.f, 0.f);
        if (c >= 48) {
            int cc = c - 48;
            v.x = fmaf(v.x, sbs[cc],     sbsh[cc]);
            v.y = fmaf(v.y, sbs[cc + 1], sbsh[cc + 1]);
            v.z = fmaf(v.z, sbs[cc + 2], sbsh[cc + 2]);
            v.w = fmaf(v.w, sbs[cc + 3], sbsh[cc + 3]);
        }
        *(float4*)&sX[rr * 116 + c] = v;
    }
    __syncthreads();

    // ---- Layer 1: [64x112] @ [112x64], thread tile 4 rows x 4 cols ----
    int tx = tid & 15, ty = tid >> 4;
    int c0 = tx * 4, r0 = ty * 4;
    {
        float4 binit = make_float4(sb1[c0], sb1[c0 + 1], sb1[c0 + 2], sb1[c0 + 3]);
        float4 acc0 = binit, acc1 = binit, acc2 = binit, acc3 = binit;
        #pragma unroll 2
        for (int k = 0; k < XDIM; k += 4) {
            float4 x0 = *(const float4*)&sX[(r0 + 0) * 116 + k];
            float4 x1 = *(const float4*)&sX[(r0 + 1) * 116 + k];
            float4 x2 = *(const float4*)&sX[(r0 + 2) * 116 + k];
            float4 x3 = *(const float4*)&sX[(r0 + 3) * 116 + k];
            float4 w0 = *(const float4*)&W1[(k + 0) * 64 + c0];
            float4 w1 = *(const float4*)&W1[(k + 1) * 64 + c0];
            float4 w2 = *(const float4*)&W1[(k + 2) * 64 + c0];
            float4 w3 = *(const float4*)&W1[(k + 3) * 64 + c0];
            fma4(acc0, x0.x, w0); fma4(acc0, x0.y, w1); fma4(acc0, x0.z, w2); fma4(acc0, x0.w, w3);
            fma4(acc1, x1.x, w0); fma4(acc1, x1.y, w1); fma4(acc1, x1.z, w2); fma4(acc1, x1.w, w3);
            fma4(acc2, x2.x, w0); fma4(acc2, x2.y, w1); fma4(acc2, x2.z, w2); fma4(acc2, x2.w, w3);
            fma4(acc3, x3.x, w0); fma4(acc3, x3.y, w1); fma4(acc3, x3.z, w2); fma4(acc3, x3.w, w3);
        }
        __syncthreads();   // all x reads complete before h overwrites sX
        float4 h;
        h.x = fmaxf(acc0.x, 0.f); h.y = fmaxf(acc0.y, 0.f); h.z = fmaxf(acc0.z, 0.f); h.w = fmaxf(acc0.w, 0.f);
        *(float4*)&sX[(r0 + 0) * 68 + c0] = h;
        h.x = fmaxf(acc1.x, 0.f); h.y = fmaxf(acc1.y, 0.f); h.z = fmaxf(acc1.z, 0.f); h.w = fmaxf(acc1.w, 0.f);
        *(float4*)&sX[(r0 + 1) * 68 + c0] = h;
        h.x = fmaxf(acc2.x, 0.f); h.y = fmaxf(acc2.y, 0.f); h.z = fmaxf(acc2.z, 0.f); h.w = fmaxf(acc2.w, 0.f);
        *(float4*)&sX[(r0 + 2) * 68 + c0] = h;
        h.x = fmaxf(acc3.x, 0.f); h.y = fmaxf(acc3.y, 0.f); h.z = fmaxf(acc3.z, 0.f); h.w = fmaxf(acc3.w, 0.f);
        *(float4*)&sX[(r0 + 3) * 68 + c0] = h;
        __syncthreads();
    }

    // ---- Layer 2: [64x64] @ [64x32], thread tile 2 rows x 4 cols ----
    {
        int tx2 = tid & 7, ty2 = tid >> 3;
        int d0 = tx2 * 4, s0 = ty2 * 2;
        float4 binit = make_float4(sb2[d0], sb2[d0 + 1], sb2[d0 + 2], sb2[d0 + 3]);
        float4 a0 = binit, a1 = binit;
        #pragma unroll 4
        for (int k = 0; k < 64; k += 4) {
            float4 h0 = *(const float4*)&sX[(s0 + 0) * 68 + k];
            float4 h1 = *(const float4*)&sX[(s0 + 1) * 68 + k];
            float4 w0 = *(const float4*)&W2[(k + 0) * 32 + d0];
            float4 w1 = *(const float4*)&W2[(k + 1) * 32 + d0];
            float4 w2 = *(const float4*)&W2[(k + 2) * 32 + d0];
            float4 w3 = *(const float4*)&W2[(k + 3) * 32 + d0];
            fma4(a0, h0.x, w0); fma4(a0, h0.y, w1); fma4(a0, h0.z, w2); fma4(a0, h0.w, w3);
            fma4(a1, h1.x, w0); fma4(a1, h1.y, w1); fma4(a1, h1.z, w2); fma4(a1, h1.w, w3);
        }
        float4 h;
        h.x = fmaxf(a0.x, 0.f); h.y = fmaxf(a0.y, 0.f); h.z = fmaxf(a0.z, 0.f); h.w = fmaxf(a0.w, 0.f);
        *(float4*)&sH2[(s0 + 0) * 36 + d0] = h;
        h.x = fmaxf(a1.x, 0.f); h.y = fmaxf(a1.y, 0.f); h.z = fmaxf(a1.z, 0.f); h.w = fmaxf(a1.w, 0.f);
        *(float4*)&sH2[(s0 + 1) * 36 + d0] = h;
        __syncthreads();
    }

    // ---- Layer 3 + sigmoid: one thread per row ----
    if (tid < 64) {
        float t = sb3v;
        const float* h2 = &sH2[tid * 36];
        #pragma unroll 8
        for (int k = 0; k < 32; k++) t = fmaf(h2[k], sW3[k], t);
        int row = rowbase + tid;
        if (row < B) out[row] = 1.f / (1.f + expf(-t));
    }
}

// ---------------------------------------------------------------------------
// Launch
// ---------------------------------------------------------------------------
extern "C" void kernel_launch(void* const* d_in, const int* in_sizes, int n_in,
                              void* d_out, int out_size)
{
    int B = in_sizes[0];
    if (B > BMAX) B = BMAX;

    bool ok = (n_in == 27)
        && in_sizes[1]  == B        && in_sizes[2]  == B
        && in_sizes[3]  == B * MAXL && in_sizes[4]  == B * MAXL
        && in_sizes[5]  == B * MAXL && in_sizes[6]  == B * MAXL
        && in_sizes[7]  == B        && in_sizes[8]  == B
        && in_sizes[9]  == B        && in_sizes[10] == B
        && in_sizes[11] == 139000 * EMB
        && in_sizes[12] == 132000 * EMB
        && in_sizes[13] == 41000 * EMB
        && in_sizes[14] == 30 * EMB
        && in_sizes[15] == 150 * EMB
        && in_sizes[16] == 132000
        && in_sizes[17] == 41000
        && in_sizes[18] == 30
        && in_sizes[19] == 64 && in_sizes[20] == 64
        && in_sizes[21] == XDIM * 64 && in_sizes[22] == 64
        && in_sizes[23] == 64 * 32   && in_sizes[24] == 32
        && in_sizes[25] == 32        && in_sizes[26] == 1;

    if (!ok) {
        fill_signal_kernel<<<(out_size + 255) / 256, 256>>>((float*)d_out, out_size);
        return;
    }

    const int* user_id  = (const int*)d_in[0];
    const int* movie_id = (const int*)d_in[1];
    const int* year     = (const int*)d_in[2];
    const int* ug       = (const int*)d_in[3];
    const int* urb      = (const int*)d_in[4];
    const int* mg       = (const int*)d_in[5];
    const int* mt       = (const int*)d_in[6];
    const int* ugc      = (const int*)d_in[7];
    const int* urbc     = (const int*)d_in[8];
    const int* mgc      = (const int*)d_in[9];
    const int* mtc      = (const int*)d_in[10];
    const float* Euser  = (const float*)d_in[11];
    const float* Emovie = (const float*)d_in[12];
    const float* Etag   = (const float*)d_in[13];
    const float* Egenre = (const float*)d_in[14];
    const float* Eyear  = (const float*)d_in[15];
    const float* Amovie = (const float*)d_in[16];
    const float* gamma  = (const float*)d_in[19];
    const float* beta   = (const float*)d_in[20];
    const float* W1     = (const float*)d_in[21];
    const float* b1     = (const float*)d_in[22];
    const float* W2     = (const float*)d_in[23];
    const float* b2     = (const float*)d_in[24];
    const float* W3     = (const float*)d_in[25];
    const float* b3     = (const float*)d_in[26];

    zero_acc_kernel<<<1, 128>>>();

    pool_kernel<<<(B + 63) / 64, 256>>>(user_id, movie_id, year, ug, urb, mg, mt,
                                        ugc, urbc, mgc, mtc,
                                        Euser, Emovie, Etag, Egenre, Eyear, Amovie, B);

    bn_finalize_kernel<<<1, 64>>>(gamma, beta, 1.0 / (double)B);

    mlp_kernel<<<(B + 63) / 64, 256>>>(W1, b1, W2, b2, W3, b3, (float*)d_out, B);
}